// round 3
// baseline (speedup 1.0000x reference)
#include <cuda_runtime.h>

#define TT   4096
#define NCH  32
#define NP   511
#define PS   16
#define NTHREADS 256

// db4 decomposition filters (ptwt convention)
__device__ __constant__ float c_lo[8] = {
    -0.010597401784997278f,  0.032883011666982945f,  0.030841381835986965f,
    -0.18703481171888114f,  -0.02798376941698385f,   0.6308807679295904f,
     0.7148465705525415f,    0.23037781330885523f
};
__device__ __constant__ float c_hi[8] = {
    -0.23037781330885523f,   0.7148465705525415f,   -0.6308807679295904f,
    -0.02798376941698385f,   0.18703481171888114f,   0.030841381835986965f,
    -0.032883011666982945f, -0.010597401784997278f
};

// One SWT stage with dilation d: coef[t] = sum_j f[j] * in[(t + d*(4-j)) mod T]
__device__ __forceinline__ void swt_stage(const float* __restrict__ in,
                                          float* __restrict__ outA,
                                          float* __restrict__ outD,
                                          int d, int tid)
{
    #pragma unroll 4
    for (int t = tid; t < TT; t += NTHREADS) {
        float lo = 0.f, hi = 0.f;
        #pragma unroll
        for (int j = 0; j < 8; j++) {
            float v = in[(t + TT + d * (4 - j)) & (TT - 1)];
            lo = fmaf(c_lo[j], v, lo);
            hi = fmaf(c_hi[j], v, hi);
        }
        outA[t] = lo;
        outD[t] = hi;
    }
}

// Scatter one coefficient band into the patched output layout.
// out[((b*NP + p)*128 + n*4 + c)*16 + s] = buf[8*p + s]
__device__ __forceinline__ void write_coeff(const float* __restrict__ buf,
                                            float* __restrict__ out,
                                            int b, int n, int c, int tid)
{
    float* dst = out + (size_t)b * NP * 2048 + (size_t)(n * 4 + c) * 16;
    #pragma unroll 4
    for (int i = tid; i < NP * PS; i += NTHREADS) {
        int p = i >> 4;
        int s = i & 15;
        dst[(size_t)p * 2048 + s] = buf[(p << 3) + s];
    }
}

__global__ __launch_bounds__(NTHREADS)
void swt_patch_kernel(const float* __restrict__ x, float* __restrict__ out)
{
    __shared__ float sA[TT];
    __shared__ float sB[TT];
    __shared__ float sC[TT];

    const int b   = blockIdx.x >> 5;   // / 32
    const int n   = blockIdx.x & 31;
    const int tid = threadIdx.x;

    // Load row x[b, :, n] (stride-32 gather; whole input fits in L2)
    const float* xin = x + (size_t)b * TT * NCH + n;
    #pragma unroll 4
    for (int t = tid; t < TT; t += NTHREADS)
        sA[t] = xin[(size_t)t * NCH];
    __syncthreads();

    // Level 1 (d=1): a1 -> sB, d1 -> sC
    swt_stage(sA, sB, sC, 1, tid);
    __syncthreads();
    write_coeff(sC, out, b, n, 3, tid);   // cD1 -> channel 3
    __syncthreads();

    // Level 2 (d=2): a2 -> sA, d2 -> sC
    swt_stage(sB, sA, sC, 2, tid);
    __syncthreads();
    write_coeff(sC, out, b, n, 2, tid);   // cD2 -> channel 2
    __syncthreads();

    // Level 3 (d=4): a3 -> sB, d3 -> sC
    swt_stage(sA, sB, sC, 4, tid);
    __syncthreads();
    write_coeff(sB, out, b, n, 0, tid);   // cA3 -> channel 0
    write_coeff(sC, out, b, n, 1, tid);   // cD3 -> channel 1
}

extern "C" void kernel_launch(void* const* d_in, const int* in_sizes, int n_in,
                              void* d_out, int out_size)
{
    const float* x = (const float*)d_in[0];
    float* out = (float*)d_out;
    (void)in_sizes; (void)n_in; (void)out_size;
    swt_patch_kernel<<<64 * 32, NTHREADS>>>(x, out);
}

// round 4
// speedup vs baseline: 1.4586x; 1.4586x over previous
#include <cuda_runtime.h>

#define TT   4096
#define NCH  32
#define NB   64
#define NP   511
#define PS   16
#define NTHREADS 256

// Transposed input scratch: xT[b][n][t], contiguous in t.
__device__ float g_xT[(size_t)NB * NCH * TT];

// db4 decomposition filters (ptwt convention)
__device__ __constant__ float c_lo[8] = {
    -0.010597401784997278f,  0.032883011666982945f,  0.030841381835986965f,
    -0.18703481171888114f,  -0.02798376941698385f,   0.6308807679295904f,
     0.7148465705525415f,    0.23037781330885523f
};
__device__ __constant__ float c_hi[8] = {
    -0.23037781330885523f,   0.7148465705525415f,   -0.6308807679295904f,
    -0.02798376941698385f,   0.18703481171888114f,   0.030841381835986965f,
    -0.032883011666982945f, -0.010597401784997278f
};

// ---------------------------------------------------------------------------
// Kernel A: transpose (B, T, N) -> (B, N, T) with 32x32 SMEM tiles.
// ---------------------------------------------------------------------------
__global__ __launch_bounds__(256)
void transpose_kernel(const float* __restrict__ x)
{
    __shared__ float tile[32][33];
    const int b  = blockIdx.y;
    const int t0 = blockIdx.x << 5;
    const int tx = threadIdx.x;
    const int ty = threadIdx.y;

    const float* src = x + ((size_t)b * TT + t0) * NCH;
    #pragma unroll
    for (int k = 0; k < 4; k++) {
        int tl = ty + (k << 3);
        tile[tl][tx] = src[(size_t)tl * NCH + tx];
    }
    __syncthreads();
    #pragma unroll
    for (int k = 0; k < 4; k++) {
        int n = ty + (k << 3);
        g_xT[((size_t)b * NCH + n) * TT + t0 + tx] = tile[tx][n];
    }
}

// ---------------------------------------------------------------------------
// One SWT stage, vectorized: each thread computes 4 consecutive outputs.
// coef[t] = sum_j f[j] * in[(t + D*(4-j)) mod T]
// Window per 4 outputs: [t0 + S, t0 + S + W), S/W multiples of 4.
// ---------------------------------------------------------------------------
template<int D, int S, int W>
__device__ __forceinline__ void swt_stage(const float* __restrict__ in,
                                          float* __restrict__ outA,
                                          float* __restrict__ outD,
                                          int tid)
{
    #pragma unroll
    for (int k = 0; k < TT / 4 / NTHREADS; k++) {
        const int t0 = ((tid + k * NTHREADS) << 2);
        float w[W];
        #pragma unroll
        for (int q = 0; q < W / 4; q++) {
            const float4 v = *(const float4*)&in[(t0 + S + 4 * q + TT) & (TT - 1)];
            w[4 * q + 0] = v.x; w[4 * q + 1] = v.y;
            w[4 * q + 2] = v.z; w[4 * q + 3] = v.w;
        }
        float lo[4], hi[4];
        #pragma unroll
        for (int e = 0; e < 4; e++) {
            float l = 0.f, h = 0.f;
            #pragma unroll
            for (int j = 0; j < 8; j++) {
                const float v = w[e + D * (4 - j) - S];
                l = fmaf(c_lo[j], v, l);
                h = fmaf(c_hi[j], v, h);
            }
            lo[e] = l; hi[e] = h;
        }
        *(float4*)&outA[t0] = make_float4(lo[0], lo[1], lo[2], lo[3]);
        *(float4*)&outD[t0] = make_float4(hi[0], hi[1], hi[2], hi[3]);
    }
}

// ---------------------------------------------------------------------------
// Scatter one coefficient band into the patched output layout (float4).
// out[((b*NP + p)*128 + n*4 + c)*16 + s] = buf[8*p + s]
// ---------------------------------------------------------------------------
__device__ __forceinline__ void write_coeff(const float* __restrict__ buf,
                                            float* __restrict__ out,
                                            int b, int n, int c, int tid)
{
    float* dst = out + (size_t)b * NP * 2048 + (size_t)(n * 4 + c) * 16;
    for (int i = tid; i < NP * PS / 4; i += NTHREADS) {
        const int p  = i >> 2;
        const int s4 = (i & 3) << 2;
        const float4 v = *(const float4*)&buf[(p << 3) + s4];
        *(float4*)&dst[(size_t)p * 2048 + s4] = v;
    }
}

// ---------------------------------------------------------------------------
// Kernel B: per-(b,n) row — 3-level SWT + patch scatter.
// ---------------------------------------------------------------------------
__global__ __launch_bounds__(NTHREADS)
void swt_patch_kernel(float* __restrict__ out)
{
    __shared__ __align__(16) float sA[TT];
    __shared__ __align__(16) float sB[TT];
    __shared__ __align__(16) float sC[TT];

    const int b   = blockIdx.x >> 5;
    const int n   = blockIdx.x & 31;
    const int tid = threadIdx.x;

    // Contiguous float4 load of the transposed row (L2-resident).
    const float4* xin = (const float4*)&g_xT[((size_t)b * NCH + n) * TT];
    #pragma unroll
    for (int k = 0; k < TT / 4 / NTHREADS; k++) {
        const int i = tid + k * NTHREADS;
        *(float4*)&sA[i << 2] = xin[i];
    }
    __syncthreads();

    // Level 1 (d=1): a1 -> sB, d1 -> sC
    swt_stage<1, -4, 12>(sA, sB, sC, tid);
    __syncthreads();
    write_coeff(sC, out, b, n, 3, tid);   // cD1 -> channel 3
    __syncthreads();

    // Level 2 (d=2): a2 -> sA, d2 -> sC
    swt_stage<2, -8, 20>(sB, sA, sC, tid);
    __syncthreads();
    write_coeff(sC, out, b, n, 2, tid);   // cD2 -> channel 2
    __syncthreads();

    // Level 3 (d=4): a3 -> sB, d3 -> sC
    swt_stage<4, -12, 32>(sA, sB, sC, tid);
    __syncthreads();
    write_coeff(sB, out, b, n, 0, tid);   // cA3 -> channel 0
    write_coeff(sC, out, b, n, 1, tid);   // cD3 -> channel 1
}

extern "C" void kernel_launch(void* const* d_in, const int* in_sizes, int n_in,
                              void* d_out, int out_size)
{
    const float* x = (const float*)d_in[0];
    float* out = (float*)d_out;
    (void)in_sizes; (void)n_in; (void)out_size;

    dim3 tgrid(TT / 32, NB);
    dim3 tblk(32, 8);
    transpose_kernel<<<tgrid, tblk>>>(x);
    swt_patch_kernel<<<NB * NCH, NTHREADS>>>(out);
}

// round 5
// speedup vs baseline: 1.5443x; 1.0588x over previous
#include <cuda_runtime.h>

#define TT   4096
#define NCH  32
#define NB   64
#define NP   511
#define PS   16
#define NTHREADS 256

// Transposed input scratch: xT[b][n][t], contiguous in t.
__device__ float g_xT[(size_t)NB * NCH * TT];

// db4 decomposition filters (ptwt convention)
__device__ __constant__ float c_lo[8] = {
    -0.010597401784997278f,  0.032883011666982945f,  0.030841381835986965f,
    -0.18703481171888114f,  -0.02798376941698385f,   0.6308807679295904f,
     0.7148465705525415f,    0.23037781330885523f
};
__device__ __constant__ float c_hi[8] = {
    -0.23037781330885523f,   0.7148465705525415f,   -0.6308807679295904f,
    -0.02798376941698385f,   0.18703481171888114f,   0.030841381835986965f,
    -0.032883011666982945f, -0.010597401784997278f
};

// ---------------------------------------------------------------------------
// Kernel A: transpose (B, T, N) -> (B, N, T), float4 on both sides.
// Block: 256 threads handle a 32t x 32n tile.
// ---------------------------------------------------------------------------
__global__ __launch_bounds__(256)
void transpose_kernel(const float* __restrict__ x)
{
    __shared__ float tile[32][33];
    const int b   = blockIdx.y;
    const int t0  = blockIdx.x << 5;
    const int lin = threadIdx.x;

    // Read: float4 along n. lin -> (t = lin>>3, nq = lin&7)
    {
        const int t  = lin >> 3;
        const int n4 = (lin & 7) << 2;
        const float4 v = *(const float4*)&x[((size_t)b * TT + t0 + t) * NCH + n4];
        tile[t][n4 + 0] = v.x;
        tile[t][n4 + 1] = v.y;
        tile[t][n4 + 2] = v.z;
        tile[t][n4 + 3] = v.w;
    }
    __syncthreads();

    // Write: float4 along t. lin -> (n = lin>>3, tq = lin&7)
    {
        const int n  = lin >> 3;
        const int t4 = (lin & 7) << 2;
        float4 v;
        v.x = tile[t4 + 0][n];
        v.y = tile[t4 + 1][n];
        v.z = tile[t4 + 2][n];
        v.w = tile[t4 + 3][n];
        *(float4*)&g_xT[((size_t)b * NCH + n) * TT + t0 + t4] = v;
    }
}

// ---------------------------------------------------------------------------
// Scatter 4 consecutive coefficient values (t0..t0+3, t0 % 4 == 0) directly
// into the patched output layout for one band:
//   value at t -> patch q=t/8 (s = t%8) and patch q-1 (s = t%8 + 8)
// dst points at out[b][.][band_channel][0] (patch stride 2048 floats).
// ---------------------------------------------------------------------------
__device__ __forceinline__ void scatter4(float4 v, float* __restrict__ dst, int t0)
{
    const int q = t0 >> 3;
    const int r = t0 & 7;            // 0 or 4
    if (q < NP)
        *(float4*)&dst[(size_t)q * 2048 + r] = v;
    if (q > 0)
        *(float4*)&dst[(size_t)(q - 1) * 2048 + r + 8] = v;
}

// ---------------------------------------------------------------------------
// One SWT stage, vectorized: each thread computes 4 consecutive outputs.
// coef[t] = sum_j f[j] * in[(t + D*(4-j)) mod T]
// lo (approx) -> SMEM (if LO_SMEM) and/or scattered to gLo (if LO_GMEM);
// hi (detail) -> always scattered to gHi.
// ---------------------------------------------------------------------------
template<int D, int S, int W, bool LO_SMEM, bool LO_GMEM>
__device__ __forceinline__ void swt_stage(const float* __restrict__ in,
                                          float* __restrict__ smemLo,
                                          float* __restrict__ gLo,
                                          float* __restrict__ gHi,
                                          int tid)
{
    #pragma unroll
    for (int k = 0; k < TT / 4 / NTHREADS; k++) {
        const int t0 = ((tid + k * NTHREADS) << 2);
        float w[W];
        #pragma unroll
        for (int q = 0; q < W / 4; q++) {
            const float4 v = *(const float4*)&in[(t0 + S + 4 * q + TT) & (TT - 1)];
            w[4 * q + 0] = v.x; w[4 * q + 1] = v.y;
            w[4 * q + 2] = v.z; w[4 * q + 3] = v.w;
        }
        float lo[4], hi[4];
        #pragma unroll
        for (int e = 0; e < 4; e++) {
            float l = 0.f, h = 0.f;
            #pragma unroll
            for (int j = 0; j < 8; j++) {
                const float v = w[e + D * (4 - j) - S];
                l = fmaf(c_lo[j], v, l);
                h = fmaf(c_hi[j], v, h);
            }
            lo[e] = l; hi[e] = h;
        }
        const float4 vlo = make_float4(lo[0], lo[1], lo[2], lo[3]);
        const float4 vhi = make_float4(hi[0], hi[1], hi[2], hi[3]);
        if (LO_SMEM) *(float4*)&smemLo[t0] = vlo;
        if (LO_GMEM) scatter4(vlo, gLo, t0);
        scatter4(vhi, gHi, t0);
    }
}

// ---------------------------------------------------------------------------
// Kernel B: per-(b,n) row — 3-level SWT, coefficients scattered straight
// from registers into the patched output.
// ---------------------------------------------------------------------------
__global__ __launch_bounds__(NTHREADS)
void swt_patch_kernel(float* __restrict__ out)
{
    __shared__ __align__(16) float sA[TT];
    __shared__ __align__(16) float sB[TT];

    const int b   = blockIdx.x >> 5;
    const int n   = blockIdx.x & 31;
    const int tid = threadIdx.x;

    // Band base pointers: out[((b*NP + p)*128 + n*4 + c)*16 + s]
    float* dstBase = out + (size_t)b * NP * 2048 + (size_t)n * 64;
    float* dst_cA3 = dstBase;           // channel 0
    float* dst_cD3 = dstBase + 16;      // channel 1
    float* dst_cD2 = dstBase + 32;      // channel 2
    float* dst_cD1 = dstBase + 48;      // channel 3

    // Contiguous float4 load of the transposed row (L2-resident).
    const float4* xin = (const float4*)&g_xT[((size_t)b * NCH + n) * TT];
    #pragma unroll
    for (int k = 0; k < TT / 4 / NTHREADS; k++) {
        const int i = tid + k * NTHREADS;
        *(float4*)&sA[i << 2] = xin[i];
    }
    __syncthreads();

    // Level 1 (d=1): cA1 -> sB, cD1 -> gmem
    swt_stage<1, -4, 12, true, false>(sA, sB, nullptr, dst_cD1, tid);
    __syncthreads();

    // Level 2 (d=2): cA2 -> sA, cD2 -> gmem
    swt_stage<2, -8, 20, true, false>(sB, sA, nullptr, dst_cD2, tid);
    __syncthreads();

    // Level 3 (d=4): cA3 -> gmem, cD3 -> gmem
    swt_stage<4, -12, 32, false, true>(sA, nullptr, dst_cA3, dst_cD3, tid);
}

extern "C" void kernel_launch(void* const* d_in, const int* in_sizes, int n_in,
                              void* d_out, int out_size)
{
    const float* x = (const float*)d_in[0];
    float* out = (float*)d_out;
    (void)in_sizes; (void)n_in; (void)out_size;

    dim3 tgrid(TT / 32, NB);
    transpose_kernel<<<tgrid, 256>>>(x);
    swt_patch_kernel<<<NB * NCH, NTHREADS>>>(out);
}